// round 13
// baseline (speedup 1.0000x reference)
#include <cuda_runtime.h>
#include <cuda_bf16.h>
#include <cstdint>

// Problem constants
#define S_LEN 2048
#define B_SZ 4
#define HID 2048
#define T_TOK 8192
#define FF 1408
#define FF2 2816
#define NEXP 8
#define NROWS 16384

// ---------------- scratch (device globals) ----------------
__device__ int   d_counts[NEXP];
__device__ int   d_offsets[NEXP + 1];
__device__ int   d_cursor[NEXP];
__device__ int   d_ea[T_TOK];
__device__ int   d_eb[T_TOK];
__device__ float d_wa[T_TOK];
__device__ float d_wb[T_TOK];
__device__ int   d_row_token[NROWS];
__device__ int   d_token_pos[T_TOK * 2];
__device__ int   d_mma_ok;
__device__ int   d_bad1;
__device__ int   d_bad2;

__device__ __align__(16) __nv_bfloat16 d_a_hi[(size_t)NROWS * HID];
__device__ __align__(16) __nv_bfloat16 d_a_lo[(size_t)NROWS * HID];
__device__ __align__(16) __nv_bfloat16 d_g_hi[(size_t)NROWS * FF];
__device__ __align__(16) __nv_bfloat16 d_g_lo[(size_t)NROWS * FF];
__device__ __align__(16) __nv_bfloat16 d_w1_hi[(size_t)NEXP * HID * FF2];
__device__ __align__(16) __nv_bfloat16 d_w1_lo[(size_t)NEXP * HID * FF2];
__device__ __align__(16) __nv_bfloat16 d_w2_hi[(size_t)NEXP * FF * HID];
__device__ __align__(16) __nv_bfloat16 d_w2_lo[(size_t)NEXP * FF * HID];
__device__ float d_h[(size_t)NROWS * FF2];
__device__ float d_g[(size_t)NROWS * FF];
__device__ float d_y[(size_t)NROWS * HID];

// ---------------- helpers ----------------
__device__ __forceinline__ void mma16816(float* c, const uint32_t* a, const uint32_t* b) {
    asm volatile(
        "mma.sync.aligned.m16n8k16.row.col.f32.bf16.bf16.f32 "
        "{%0,%1,%2,%3}, {%4,%5,%6,%7}, {%8,%9}, {%0,%1,%2,%3};"
        : "+f"(c[0]), "+f"(c[1]), "+f"(c[2]), "+f"(c[3])
        : "r"(a[0]), "r"(a[1]), "r"(a[2]), "r"(a[3]), "r"(b[0]), "r"(b[1]));
}

__device__ __forceinline__ float synthA(int m, int k) {
    return 0.01f * (float)((m * 7 + k * 13 + 3) % 31 - 15);
}
__device__ __forceinline__ float synthB(int k, int n) {
    return 0.01f * (float)((k * 11 + n * 5 + 1) % 29 - 14);
}

// ---------------- smoke A: single warp, single mma ----------------
__global__ void mma_smoke_kernel() {
    __shared__ __nv_bfloat16 tA[16][16];
    __shared__ __nv_bfloat16 tB[16][8];
    int lane = threadIdx.x;
    for (int i = lane; i < 256; i += 32)
        tA[i / 16][i % 16] = __float2bfloat16(0.1f * ((i * 7 + 3) % 13) - 0.6f);
    for (int i = lane; i < 128; i += 32)
        tB[i / 8][i % 8] = __float2bfloat16(0.1f * ((i * 5 + 1) % 11) - 0.5f);
    __syncwarp();
    int fr = lane >> 2, fcp = (lane & 3) * 2;
    uint32_t a[4], b[2];
    a[0] = *(const uint32_t*)&tA[fr][fcp];
    a[1] = *(const uint32_t*)&tA[fr + 8][fcp];
    a[2] = *(const uint32_t*)&tA[fr][fcp + 8];
    a[3] = *(const uint32_t*)&tA[fr + 8][fcp + 8];
    b[0] = (uint32_t)*(const uint16_t*)&tB[fcp][fr]
         | ((uint32_t)*(const uint16_t*)&tB[fcp + 1][fr] << 16);
    b[1] = (uint32_t)*(const uint16_t*)&tB[fcp + 8][fr]
         | ((uint32_t)*(const uint16_t*)&tB[fcp + 9][fr] << 16);
    float c[4] = {0.f, 0.f, 0.f, 0.f};
    mma16816(c, a, b);
    bool ok = true;
    int rows[2] = {fr, fr + 8};
#pragma unroll
    for (int h = 0; h < 2; h++)
#pragma unroll
        for (int q = 0; q < 2; q++) {
            float ref = 0.f;
            for (int k = 0; k < 16; k++)
                ref += __bfloat162float(tA[rows[h]][k]) * __bfloat162float(tB[k][fcp + q]);
            if (fabsf(c[h * 2 + q] - ref) > 1e-3f) ok = false;
        }
    unsigned m = __ballot_sync(0xffffffffu, ok);
    if (lane == 0) d_mma_ok = (m == 0xffffffffu) ? 1 : 0;
}

// ---------------- smoke C: full-tile replica of mma_min, in-kernel reference -------
// 1 CTA, 256 threads, M=128 N=128 K=64 (2 k-chunks), same smem layouts, same
// manual fragment loads, same 3-pass hi/lo chained accumulation.
__global__ void mma_tile_smoke_kernel() {
    if (d_mma_ok == 0) return;
    constexpr int Kt = 64;
    __shared__ __align__(16) __nv_bfloat16 sA[2][128][40];
    __shared__ __align__(16) __nv_bfloat16 sB[2][32][136];

    int tid = threadIdx.x, wid = tid >> 5, lane = tid & 31;
    int wm = wid >> 2, wn = wid & 3;
    int fr = lane >> 2, fcp = (lane & 3) * 2;

    float acc[4][4][4];
#pragma unroll
    for (int i = 0; i < 4; i++)
#pragma unroll
        for (int j = 0; j < 4; j++)
#pragma unroll
            for (int q = 0; q < 4; q++) acc[i][j][q] = 0.f;

    int fa_row = tid >> 1, fa_off = (tid & 1) * 16;
    int fb_row = tid >> 3, fb_off = (tid & 7) * 16;

    for (int kc = 0; kc < Kt / 32; kc++) {
        __syncthreads();
        for (int kk = 0; kk < 16; kk++) {
            float v = synthA(fa_row, kc * 32 + fa_off + kk);
            __nv_bfloat16 h = __float2bfloat16(v);
            sA[0][fa_row][fa_off + kk] = h;
            sA[1][fa_row][fa_off + kk] = __float2bfloat16(v - __bfloat162float(h));
        }
        for (int nn = 0; nn < 16; nn++) {
            float v = synthB(kc * 32 + fb_row, fb_off + nn);
            __nv_bfloat16 h = __float2bfloat16(v);
            sB[0][fb_row][fb_off + nn] = h;
            sB[1][fb_row][fb_off + nn] = __float2bfloat16(v - __bfloat162float(h));
        }
        __syncthreads();

#pragma unroll
        for (int s = 0; s < 2; s++) {
            uint32_t ah[4][4], al[4][4], bh[4][2], bl[4][2];
#pragma unroll
            for (int mt = 0; mt < 4; mt++) {
                const __nv_bfloat16* b0 = &sA[0][wm * 64 + mt * 16 + fr][s * 16 + fcp];
                const __nv_bfloat16* b1 = &sA[1][wm * 64 + mt * 16 + fr][s * 16 + fcp];
                ah[mt][0] = *(const uint32_t*)b0;
                ah[mt][1] = *(const uint32_t*)(b0 + 8 * 40);
                ah[mt][2] = *(const uint32_t*)(b0 + 8);
                ah[mt][3] = *(const uint32_t*)(b0 + 8 * 40 + 8);
                al[mt][0] = *(const uint32_t*)b1;
                al[mt][1] = *(const uint32_t*)(b1 + 8 * 40);
                al[mt][2] = *(const uint32_t*)(b1 + 8);
                al[mt][3] = *(const uint32_t*)(b1 + 8 * 40 + 8);
            }
#pragma unroll
            for (int nt = 0; nt < 4; nt++) {
                int n = wn * 32 + nt * 8 + fr;
                int k = s * 16 + fcp;
                bh[nt][0] = (uint32_t)*(const uint16_t*)&sB[0][k][n]
                          | ((uint32_t)*(const uint16_t*)&sB[0][k + 1][n] << 16);
                bh[nt][1] = (uint32_t)*(const uint16_t*)&sB[0][k + 8][n]
                          | ((uint32_t)*(const uint16_t*)&sB[0][k + 9][n] << 16);
                bl[nt][0] = (uint32_t)*(const uint16_t*)&sB[1][k][n]
                          | ((uint32_t)*(const uint16_t*)&sB[1][k + 1][n] << 16);
                bl[nt][1] = (uint32_t)*(const uint16_t*)&sB[1][k + 8][n]
                          | ((uint32_t)*(const uint16_t*)&sB[1][k + 9][n] << 16);
            }
#pragma unroll
            for (int mt = 0; mt < 4; mt++)
#pragma unroll
                for (int nt = 0; nt < 4; nt++) {
                    mma16816(acc[mt][nt], ah[mt], bh[nt]);
                    mma16816(acc[mt][nt], ah[mt], bl[nt]);
                    mma16816(acc[mt][nt], al[mt], bh[nt]);
                }
        }
    }

    // verify every accumulator against fp32 formula reference
    bool ok = true;
    int g = lane >> 2, t4 = lane & 3;
#pragma unroll
    for (int mt = 0; mt < 4; mt++) {
        int r0 = wm * 64 + mt * 16 + g;
#pragma unroll
        for (int nt = 0; nt < 4; nt++) {
            int c = wn * 32 + nt * 8 + 2 * t4;
            float r00 = 0.f, r01 = 0.f, r10 = 0.f, r11 = 0.f;
            for (int k = 0; k < Kt; k++) {
                float av0 = synthA(r0, k), av1 = synthA(r0 + 8, k);
                float bv0 = synthB(k, c), bv1 = synthB(k, c + 1);
                r00 += av0 * bv0; r01 += av0 * bv1;
                r10 += av1 * bv0; r11 += av1 * bv1;
            }
            if (fabsf(acc[mt][nt][0] - r00) > 2e-3f) ok = false;
            if (fabsf(acc[mt][nt][1] - r01) > 2e-3f) ok = false;
            if (fabsf(acc[mt][nt][2] - r10) > 2e-3f) ok = false;
            if (fabsf(acc[mt][nt][3] - r11) > 2e-3f) ok = false;
        }
    }
    if (!ok) atomicExch(&d_mma_ok, 0);
}

// ---------------- routing ----------------
__global__ void zero_counts_kernel() {
    if (threadIdx.x < NEXP) d_counts[threadIdx.x] = 0;
    if (threadIdx.x == 0) { d_bad1 = 0; d_bad2 = 0; }
}

__global__ void gate_kernel(const float* __restrict__ x, const float* __restrict__ wg) {
    int t = blockIdx.x;
    const float* xr = x + ((size_t)(t % S_LEN) * B_SZ + (t / S_LEN)) * HID;
    float acc[NEXP];
#pragma unroll
    for (int e = 0; e < NEXP; e++) acc[e] = 0.f;
    for (int h = threadIdx.x; h < HID; h += 256) {
        float xv = xr[h];
#pragma unroll
        for (int e = 0; e < NEXP; e++) acc[e] += xv * wg[e * HID + h];
    }
#pragma unroll
    for (int e = 0; e < NEXP; e++)
        for (int off = 16; off; off >>= 1)
            acc[e] += __shfl_down_sync(0xffffffffu, acc[e], off);
    __shared__ float red[8][NEXP];
    int warp = threadIdx.x >> 5, lane = threadIdx.x & 31;
    if (lane == 0)
#pragma unroll
        for (int e = 0; e < NEXP; e++) red[warp][e] = acc[e];
    __syncthreads();
    if (threadIdx.x == 0) {
        float logits[NEXP];
#pragma unroll
        for (int e = 0; e < NEXP; e++) {
            float s = 0.f;
            for (int w = 0; w < 8; w++) s += red[w][e];
            logits[e] = s;
        }
        float m = logits[0];
#pragma unroll
        for (int e = 1; e < NEXP; e++) m = fmaxf(m, logits[e]);
        float sc[NEXP], Z = 0.f;
#pragma unroll
        for (int e = 0; e < NEXP; e++) { sc[e] = expf(logits[e] - m); Z += sc[e]; }
        float invZ = 1.f / Z;
#pragma unroll
        for (int e = 0; e < NEXP; e++) sc[e] *= invZ;
        int e0 = 0;
#pragma unroll
        for (int e = 1; e < NEXP; e++) if (sc[e] > sc[e0]) e0 = e;
        int e1 = (e0 == 0) ? 1 : 0;
#pragma unroll
        for (int e = 0; e < NEXP; e++) if (e != e0 && sc[e] > sc[e1]) e1 = e;
        float s0 = sc[e0], s1 = sc[e1];
        float inv = 1.f / (s0 + s1 + 1e-20f);
        d_ea[t] = e0; d_eb[t] = e1;
        d_wa[t] = s0 * inv; d_wb[t] = s1 * inv;
        atomicAdd(&d_counts[e0], 1);
        atomicAdd(&d_counts[e1], 1);
    }
}

__global__ void scan_kernel() {
    int o = 0;
    d_offsets[0] = 0;
#pragma unroll
    for (int e = 0; e < NEXP; e++) { o += d_counts[e]; d_offsets[e + 1] = o; }
#pragma unroll
    for (int e = 0; e < NEXP; e++) d_cursor[e] = d_offsets[e];
}

__global__ void assign_kernel() {
    int t = blockIdx.x * blockDim.x + threadIdx.x;
    if (t >= T_TOK) return;
    int p0 = atomicAdd(&d_cursor[d_ea[t]], 1);
    d_row_token[p0] = t;
    d_token_pos[2 * t] = p0;
    int p1 = atomicAdd(&d_cursor[d_eb[t]], 1);
    d_row_token[p1] = t;
    d_token_pos[2 * t + 1] = p1;
}

// ---------------- mma-path pre-passes (gated on d_mma_ok) ----------------
__global__ void gather_split_kernel(const float* __restrict__ x) {
    if (d_mma_ok == 0) return;
    int r = blockIdx.x;
    int t = d_row_token[r];
    const float2* xr = (const float2*)(x + ((size_t)(t % S_LEN) * B_SZ + (t / S_LEN)) * HID);
    __nv_bfloat162* ah = (__nv_bfloat162*)(d_a_hi + (size_t)r * HID);
    __nv_bfloat162* al = (__nv_bfloat162*)(d_a_lo + (size_t)r * HID);
    for (int j = threadIdx.x; j < HID / 2; j += 256) {
        float2 v = xr[j];
        __nv_bfloat162 h2 = __floats2bfloat162_rn(v.x, v.y);
        float r0 = v.x - __low2float(h2);
        float r1 = v.y - __high2float(h2);
        ah[j] = h2;
        al[j] = __floats2bfloat162_rn(r0, r1);
    }
}

__global__ void split_w_kernel(const float* __restrict__ W,
                               __nv_bfloat16* __restrict__ Whi,
                               __nv_bfloat16* __restrict__ Wlo, int n4) {
    if (d_mma_ok == 0) return;
    int i = blockIdx.x * blockDim.x + threadIdx.x;
    if (i >= n4) return;
    float4 v = ((const float4*)W)[i];
    __nv_bfloat162 h0 = __floats2bfloat162_rn(v.x, v.y);
    __nv_bfloat162 h1 = __floats2bfloat162_rn(v.z, v.w);
    __nv_bfloat162 l0 = __floats2bfloat162_rn(v.x - __low2float(h0), v.y - __high2float(h0));
    __nv_bfloat162 l1 = __floats2bfloat162_rn(v.z - __low2float(h1), v.w - __high2float(h1));
    ((__nv_bfloat162*)Whi)[2 * i] = h0;
    ((__nv_bfloat162*)Whi)[2 * i + 1] = h1;
    ((__nv_bfloat162*)Wlo)[2 * i] = l0;
    ((__nv_bfloat162*)Wlo)[2 * i + 1] = l1;
}

// ---------------- swiglu: always d_g fp32; hi/lo only when mma live ----------------
__global__ void swiglu_full_kernel() {
    int r = blockIdx.x;
    int mok = d_mma_ok;
    const float* hr = d_h + (size_t)r * FF2;
    float2* gf = (float2*)(d_g + (size_t)r * FF);
    __nv_bfloat162* gh = (__nv_bfloat162*)(d_g_hi + (size_t)r * FF);
    __nv_bfloat162* gl = (__nv_bfloat162*)(d_g_lo + (size_t)r * FF);
    for (int j = threadIdx.x; j < FF / 2; j += 256) {
        float2 a = ((const float2*)hr)[j];
        float2 b = ((const float2*)(hr + FF))[j];
        float y0 = (a.x / (1.f + expf(-a.x))) * b.x;
        float y1 = (a.y / (1.f + expf(-a.y))) * b.y;
        gf[j] = make_float2(y0, y1);
        if (mok) {
            __nv_bfloat162 h2 = __floats2bfloat162_rn(y0, y1);
            float r0 = y0 - __low2float(h2);
            float r1 = y1 - __high2float(h2);
            gh[j] = h2;
            gl[j] = __floats2bfloat162_rn(r0, r1);
        }
    }
}

// ---------------- bf16x3 mma GEMM, manual fragment loads ----------------
template <int MODE>
__global__ void __launch_bounds__(256, 1)
mma_min_kernel() {
    if (d_mma_ok == 0) return;
    constexpr int Kd = (MODE == 0) ? HID : FF;
    constexpr int Nd = (MODE == 0) ? FF2 : HID;
    constexpr int NC = Kd / 32;

    int e = blockIdx.z;
    int seg0 = d_offsets[e], seg1 = d_offsets[e + 1];
    int row0 = seg0 + blockIdx.x * 128;
    if (row0 >= seg1) return;
    int col0 = blockIdx.y * 128;

    __shared__ __align__(16) __nv_bfloat16 sA[2][128][40];
    __shared__ __align__(16) __nv_bfloat16 sB[2][32][136];

    int tid = threadIdx.x, wid = tid >> 5, lane = tid & 31;
    int wm = wid >> 2, wn = wid & 3;

    const __nv_bfloat16* Ah;
    const __nv_bfloat16* Al;
    const __nv_bfloat16* Wh;
    const __nv_bfloat16* Wl;
    if (MODE == 0) { Ah = d_a_hi; Al = d_a_lo; Wh = d_w1_hi; Wl = d_w1_lo; }
    else           { Ah = d_g_hi; Al = d_g_lo; Wh = d_w2_hi; Wl = d_w2_lo; }

    float acc[4][4][4];
#pragma unroll
    for (int i = 0; i < 4; i++)
#pragma unroll
        for (int j = 0; j < 4; j++)
#pragma unroll
            for (int q = 0; q < 4; q++) acc[i][j][q] = 0.f;

    int fr = lane >> 2, fcp = (lane & 3) * 2;
    int fa_row = tid >> 1, fa_off = (tid & 1) * 16;
    int fb_row = tid >> 3, fb_off = (tid & 7) * 16;
    int fa_gr = min(row0 + fa_row, NROWS - 1);

    for (int kc = 0; kc < NC; kc++) {
        __syncthreads();
        {
            const __nv_bfloat16* pH = Ah + (size_t)fa_gr * Kd + kc * 32 + fa_off;
            const __nv_bfloat16* pL = Al + (size_t)fa_gr * Kd + kc * 32 + fa_off;
            *(uint4*)&sA[0][fa_row][fa_off]     = *(const uint4*)pH;
            *(uint4*)&sA[0][fa_row][fa_off + 8] = *(const uint4*)(pH + 8);
            *(uint4*)&sA[1][fa_row][fa_off]     = *(const uint4*)pL;
            *(uint4*)&sA[1][fa_row][fa_off + 8] = *(const uint4*)(pL + 8);
            size_t wb = (size_t)e * Kd * Nd + (size_t)(kc * 32 + fb_row) * Nd + col0 + fb_off;
            const __nv_bfloat16* qH = Wh + wb;
            const __nv_bfloat16* qL = Wl + wb;
            *(uint4*)&sB[0][fb_row][fb_off]     = *(const uint4*)qH;
            *(uint4*)&sB[0][fb_row][fb_off + 8] = *(const uint4*)(qH + 8);
            *(uint4*)&sB[1][fb_row][fb_off]     = *(const uint4*)qL;
            *(uint4*)&sB[1][fb_row][fb_off + 8] = *(const uint4*)(qL + 8);
        }
        __syncthreads();

#pragma unroll
        for (int s = 0; s < 2; s++) {
            uint32_t ah[4][4], al[4][4], bh[4][2], bl[4][2];
#pragma unroll
            for (int mt = 0; mt < 4; mt++) {
                const __nv_bfloat16* b0 = &sA[0][wm * 64 + mt * 16 + fr][s * 16 + fcp];
                const __nv_bfloat16* b1 = &sA[1][wm * 64 + mt * 16 + fr][s * 16 + fcp];
                ah[mt][0] = *(const uint32_t*)b0;
                ah[mt][1] = *(const uint32_t*)(b0 + 8 * 40);
                ah[mt][2] = *(const uint32_t*)(b0 + 8);
                ah[mt][3] = *(const uint32_t*)(b0 + 8 * 40 + 8);
                al[mt][0] = *(const uint32_t*)b1;
                al[mt][1] = *(const uint32_t*)(b1 + 8 * 40);
                al[mt][2] = *(const uint32_t*)(b1 + 8);
                al[mt][3] = *(const uint32_t*)(b1 + 8 * 40 + 8);
            }
#pragma unroll
            for (int nt = 0; nt < 4; nt++) {
                int n = wn * 32 + nt * 8 + fr;
                int k = s * 16 + fcp;
                bh[nt][0] = (uint32_t)*(const uint16_t*)&sB[0][k][n]
                          | ((uint32_t)*(const uint16_t*)&sB[0][k + 1][n] << 16);
                bh[nt][1] = (uint32_t)*(const uint16_t*)&sB[0][k + 8][n]
                          | ((uint32_t)*(const uint16_t*)&sB[0][k + 9][n] << 16);
                bl[nt][0] = (uint32_t)*(const uint16_t*)&sB[1][k][n]
                          | ((uint32_t)*(const uint16_t*)&sB[1][k + 1][n] << 16);
                bl[nt][1] = (uint32_t)*(const uint16_t*)&sB[1][k + 8][n]
                          | ((uint32_t)*(const uint16_t*)&sB[1][k + 9][n] << 16);
            }
#pragma unroll
            for (int mt = 0; mt < 4; mt++)
#pragma unroll
                for (int nt = 0; nt < 4; nt++) {
                    mma16816(acc[mt][nt], ah[mt], bh[nt]);
                    mma16816(acc[mt][nt], ah[mt], bl[nt]);
                    mma16816(acc[mt][nt], al[mt], bh[nt]);
                }
        }
    }

    float* C = (MODE == 0) ? d_h : d_y;
    int g = lane >> 2, t4 = lane & 3;
#pragma unroll
    for (int mt = 0; mt < 4; mt++) {
        int rbase = row0 + wm * 64 + mt * 16;
#pragma unroll
        for (int nt = 0; nt < 4; nt++) {
            int col = col0 + wn * 32 + nt * 8 + 2 * t4;
            if (rbase + g < seg1)
                *(float2*)&C[(size_t)(rbase + g) * Nd + col] =
                    make_float2(acc[mt][nt][0], acc[mt][nt][1]);
            if (rbase + 8 + g < seg1)
                *(float2*)&C[(size_t)(rbase + 8 + g) * Nd + col] =
                    make_float2(acc[mt][nt][2], acc[mt][nt][3]);
        }
    }
}

// ---------------- sampled check of mma output ----------------
template <int MODE>
__global__ void check_kernel(const float* __restrict__ x, const float* __restrict__ W) {
    if (d_mma_ok == 0) return;
    constexpr int Kd = (MODE == 0) ? HID : FF;
    constexpr int Nd = (MODE == 0) ? FF2 : HID;
    int j = blockIdx.x;
    uint32_t h = (uint32_t)j * 2654435761u;
    int r = (int)((h >> 7) % NROWS);
    int n = (int)(((h ^ (h >> 16)) * 40503u) % (uint32_t)Nd);
    int e = 0;
#pragma unroll
    for (int q = 0; q < NEXP - 1; q++) if (r >= d_offsets[q + 1]) e = q + 1;

    const float* arow;
    if (MODE == 0) {
        int t = d_row_token[r];
        arow = x + ((size_t)(t % S_LEN) * B_SZ + (t / S_LEN)) * HID;
    } else {
        arow = d_g + (size_t)r * FF;
    }
    const float* wcol = W + (size_t)e * Kd * Nd + n;
    float p = 0.f;
    for (int k = threadIdx.x; k < Kd; k += 256)
        p += arow[k] * wcol[(size_t)k * Nd];
    for (int off = 16; off; off >>= 1) p += __shfl_down_sync(0xffffffffu, p, off);
    __shared__ float red[8];
    if ((threadIdx.x & 31) == 0) red[threadIdx.x >> 5] = p;
    __syncthreads();
    if (threadIdx.x == 0) {
        float ref = 0.f;
        for (int w = 0; w < 8; w++) ref += red[w];
        float got = (MODE == 0) ? d_h[(size_t)r * Nd + n] : d_y[(size_t)r * Nd + n];
        if (fabsf(got - ref) > 1e-2f * (fabsf(ref) + 1.f)) {
            if (MODE == 0) atomicExch(&d_bad1, 1);
            else           atomicExch(&d_bad2, 1);
        }
    }
}

// ---------------- f32x2 SIMT GEMM (proven), gated fallback ----------------
template <int MODE>
__global__ void __launch_bounds__(256, 2)
gemm2x_kernel(const float* __restrict__ Xin, const float* __restrict__ Wbase) {
    if (d_mma_ok != 0 && ((MODE == 0) ? d_bad1 : d_bad2) == 0) return;
    constexpr int Kd = (MODE == 0) ? HID : FF;
    constexpr int Nd = (MODE == 0) ? FF2 : HID;

    int e = blockIdx.z;
    int seg0 = d_offsets[e], seg1 = d_offsets[e + 1];
    int row0 = seg0 + blockIdx.x * 128;
    if (row0 >= seg1) return;
    int col0 = blockIdx.y * 128;

    const float* W = Wbase + (size_t)e * Kd * Nd + col0;

    __shared__ float As[16][128];
    __shared__ float Bs[16][128];

    int tid = threadIdx.x;
    int a_row = tid >> 1;
    int a_col = (tid & 1) * 4;
    int grow = row0 + a_row;
    bool a_valid = grow < seg1;
    const float* Arow;
    if (MODE == 0) {
        int t = a_valid ? d_row_token[grow] : 0;
        Arow = Xin + ((size_t)(t % S_LEN) * B_SZ + (t / S_LEN)) * HID;
    } else {
        Arow = d_g + (size_t)(a_valid ? grow : 0) * Kd;
    }
    int b_row = tid >> 5;
    int b_col = (tid & 31) * 4;
    const float* Wp = W + (size_t)b_row * Nd + b_col;

    int ty = tid >> 4, tx = tid & 15;

    unsigned long long acc2[8][4];
#pragma unroll
    for (int i = 0; i < 8; i++)
#pragma unroll
        for (int j = 0; j < 4; j++) acc2[i][j] = 0ull;

    for (int k0 = 0; k0 < Kd; k0 += 16) {
#pragma unroll
        for (int h = 0; h < 2; h++) {
            float4 av = a_valid ? *(const float4*)(Arow + k0 + h * 8 + a_col)
                                : make_float4(0.f, 0.f, 0.f, 0.f);
            As[h * 8 + a_col + 0][a_row] = av.x;
            As[h * 8 + a_col + 1][a_row] = av.y;
            As[h * 8 + a_col + 2][a_row] = av.z;
            As[h * 8 + a_col + 3][a_row] = av.w;
            *(float4*)&Bs[h * 8 + b_row][b_col] =
                *(const float4*)(Wp + (size_t)(k0 + h * 8) * Nd);
        }
        __syncthreads();
#pragma unroll
        for (int k = 0; k < 16; k++) {
            unsigned long long b2[4];
#pragma unroll
            for (int j = 0; j < 4; j++)
                b2[j] = *(const unsigned long long*)&Bs[k][tx * 8 + j * 2];
#pragma unroll
            for (int i = 0; i < 8; i++) {
                unsigned int a1 = __float_as_uint(As[k][ty * 8 + i]);
                unsigned long long a2;
                asm("mov.b64 %0, {%1, %1};" : "=l"(a2) : "r"(a1));
#pragma unroll
                for (int j = 0; j < 4; j++)
                    asm("fma.rn.f32x2 %0, %1, %2, %0;"
                        : "+l"(acc2[i][j]) : "l"(a2), "l"(b2[j]));
            }
        }
        __syncthreads();
    }

    float* C = (MODE == 0) ? d_h : d_y;
#pragma unroll
    for (int i = 0; i < 8; i++) {
        int gr = row0 + ty * 8 + i;
        if (gr < seg1) {
            unsigned long long* cp =
                (unsigned long long*)(C + (size_t)gr * Nd + col0 + tx * 8);
#pragma unroll
            for (int j = 0; j < 4; j++) cp[j] = acc2[i][j];
        }
    }
}

// ---------------- swiglu refresh hi/lo if gemm1 rescued ----------------
__global__ void swiglu_refresh_kernel() {
    if (d_mma_ok == 0 || d_bad1 == 0) return;
    int r = blockIdx.x;
    const float* hr = d_h + (size_t)r * FF2;
    float2* gf = (float2*)(d_g + (size_t)r * FF);
    __nv_bfloat162* gh = (__nv_bfloat162*)(d_g_hi + (size_t)r * FF);
    __nv_bfloat162* gl = (__nv_bfloat162*)(d_g_lo + (size_t)r * FF);
    for (int j = threadIdx.x; j < FF / 2; j += 256) {
        float2 a = ((const float2*)hr)[j];
        float2 b = ((const float2*)(hr + FF))[j];
        float y0 = (a.x / (1.f + expf(-a.x))) * b.x;
        float y1 = (a.y / (1.f + expf(-a.y))) * b.y;
        gf[j] = make_float2(y0, y1);
        __nv_bfloat162 h2 = __floats2bfloat162_rn(y0, y1);
        float r0 = y0 - __low2float(h2);
        float r1 = y1 - __high2float(h2);
        gh[j] = h2;
        gl[j] = __floats2bfloat162_rn(r0, r1);
    }
}

// ---------------- combine ----------------
__global__ void combine_kernel(float* __restrict__ out) {
    int v = blockIdx.x * blockDim.x + threadIdx.x;
    const int total = T_TOK * (HID / 4);
    if (v >= total) return;
    int t = v / (HID / 4);
    int h4 = v % (HID / 4);
    int p0 = d_token_pos[2 * t], p1 = d_token_pos[2 * t + 1];
    float wa = d_wa[t], wb = d_wb[t];
    const float4 y0 = *(const float4*)&d_y[(size_t)p0 * HID + h4 * 4];
    const float4 y1 = *(const float4*)&d_y[(size_t)p1 * HID + h4 * 4];
    float4 o;
    o.x = wa * y0.x + wb * y1.x;
    o.y = wa * y0.y + wb * y1.y;
    o.z = wa * y0.z + wb * y1.z;
    o.w = wa * y0.w + wb * y1.w;
    int s = t % S_LEN, b = t / S_LEN;
    *(float4*)&out[((size_t)s * B_SZ + b) * HID + h4 * 4] = o;
}

// ---------------- launch ----------------
extern "C" void kernel_launch(void* const* d_in, const int* in_sizes, int n_in,
                              void* d_out, int out_size) {
    const float* x  = (const float*)d_in[0];
    const float* wg = (const float*)d_in[1];
    const float* w1 = (const float*)d_in[2];
    const float* w2 = (const float*)d_in[3];
    float* out = (float*)d_out;

    mma_smoke_kernel<<<1, 32>>>();
    mma_tile_smoke_kernel<<<1, 256>>>();
    zero_counts_kernel<<<1, 32>>>();
    gate_kernel<<<T_TOK, 256>>>(x, wg);
    scan_kernel<<<1, 1>>>();
    assign_kernel<<<T_TOK / 256, 256>>>();

    gather_split_kernel<<<NROWS, 256>>>(x);
    int w1n4 = NEXP * HID * FF2 / 4;
    int w2n4 = NEXP * FF * HID / 4;
    split_w_kernel<<<(w1n4 + 255) / 256, 256>>>(w1, d_w1_hi, d_w1_lo, w1n4);
    split_w_kernel<<<(w2n4 + 255) / 256, 256>>>(w2, d_w2_hi, d_w2_lo, w2n4);

    mma_min_kernel<0><<<dim3(128, FF2 / 128, NEXP), 256>>>();
    check_kernel<0><<<8192, 256>>>(x, w1);
    gemm2x_kernel<0><<<dim3(128, FF2 / 128, NEXP), 256>>>(x, w1);

    swiglu_full_kernel<<<NROWS, 256>>>();
    swiglu_refresh_kernel<<<NROWS, 256>>>();

    mma_min_kernel<1><<<dim3(128, HID / 128, NEXP), 256>>>();
    check_kernel<1><<<8192, 256>>>(x, w2);
    gemm2x_kernel<1><<<dim3(128, HID / 128, NEXP), 256>>>(nullptr, w2);

    combine_kernel<<<(T_TOK * (HID / 4)) / 256, 256>>>(out);
}

// round 14
// speedup vs baseline: 1.7652x; 1.7652x over previous
#include <cuda_runtime.h>
#include <cstdint>

// Problem constants
#define S_LEN 2048
#define B_SZ 4
#define HID 2048
#define T_TOK 8192
#define FF 1408
#define FF2 2816
#define NEXP 8
#define NROWS 16384
#define BK 16

// ---------------- scratch (device globals) ----------------
__device__ int   d_counts[NEXP];
__device__ int   d_offsets[NEXP + 1];
__device__ int   d_cursor[NEXP];
__device__ int   d_ea[T_TOK];
__device__ int   d_eb[T_TOK];
__device__ float d_wa[T_TOK];
__device__ float d_wb[T_TOK];
__device__ int   d_row_token[NROWS];
__device__ int   d_token_pos[T_TOK * 2];
__device__ float d_h[(size_t)NROWS * FF2];
__device__ float d_g[(size_t)NROWS * FF];
__device__ float d_y[(size_t)NROWS * HID];

// ---------------- routing ----------------
__global__ void zero_counts_kernel() {
    if (threadIdx.x < NEXP) d_counts[threadIdx.x] = 0;
}

// 4 tokens per block: wg loads amortized 4x. Per-token FP order identical to the
// proven 1-token version (same h-striding, same shuffle tree, same warp-sum order),
// so routing decisions are bit-identical.
__global__ void gate_kernel(const float* __restrict__ x, const float* __restrict__ wg) {
    int t0 = blockIdx.x * 4;
    const float* xr[4];
#pragma unroll
    for (int q = 0; q < 4; q++) {
        int t = t0 + q;
        xr[q] = x + ((size_t)(t % S_LEN) * B_SZ + (t / S_LEN)) * HID;
    }
    float acc[4][NEXP];
#pragma unroll
    for (int q = 0; q < 4; q++)
#pragma unroll
        for (int e = 0; e < NEXP; e++) acc[q][e] = 0.f;

    for (int h = threadIdx.x; h < HID; h += 256) {
        float wv[NEXP];
#pragma unroll
        for (int e = 0; e < NEXP; e++) wv[e] = wg[e * HID + h];
#pragma unroll
        for (int q = 0; q < 4; q++) {
            float xv = xr[q][h];
#pragma unroll
            for (int e = 0; e < NEXP; e++) acc[q][e] += xv * wv[e];
        }
    }
#pragma unroll
    for (int q = 0; q < 4; q++)
#pragma unroll
        for (int e = 0; e < NEXP; e++)
            for (int off = 16; off; off >>= 1)
                acc[q][e] += __shfl_down_sync(0xffffffffu, acc[q][e], off);

    __shared__ float red[8][4][NEXP];
    int warp = threadIdx.x >> 5, lane = threadIdx.x & 31;
    if (lane == 0)
#pragma unroll
        for (int q = 0; q < 4; q++)
#pragma unroll
            for (int e = 0; e < NEXP; e++) red[warp][q][e] = acc[q][e];
    __syncthreads();

    if (threadIdx.x < 4) {
        int q = threadIdx.x;
        int t = t0 + q;
        float logits[NEXP];
#pragma unroll
        for (int e = 0; e < NEXP; e++) {
            float s = 0.f;
            for (int w = 0; w < 8; w++) s += red[w][q][e];
            logits[e] = s;
        }
        float m = logits[0];
#pragma unroll
        for (int e = 1; e < NEXP; e++) m = fmaxf(m, logits[e]);
        float sc[NEXP], Z = 0.f;
#pragma unroll
        for (int e = 0; e < NEXP; e++) { sc[e] = expf(logits[e] - m); Z += sc[e]; }
        float invZ = 1.f / Z;
#pragma unroll
        for (int e = 0; e < NEXP; e++) sc[e] *= invZ;
        int e0 = 0;
#pragma unroll
        for (int e = 1; e < NEXP; e++) if (sc[e] > sc[e0]) e0 = e;
        int e1 = (e0 == 0) ? 1 : 0;
#pragma unroll
        for (int e = 0; e < NEXP; e++) if (e != e0 && sc[e] > sc[e1]) e1 = e;
        float s0 = sc[e0], s1 = sc[e1];
        float inv = 1.f / (s0 + s1 + 1e-20f);
        d_ea[t] = e0; d_eb[t] = e1;
        d_wa[t] = s0 * inv; d_wb[t] = s1 * inv;
        atomicAdd(&d_counts[e0], 1);
        atomicAdd(&d_counts[e1], 1);
    }
}

__global__ void scan_kernel() {
    int o = 0;
    d_offsets[0] = 0;
#pragma unroll
    for (int e = 0; e < NEXP; e++) { o += d_counts[e]; d_offsets[e + 1] = o; }
#pragma unroll
    for (int e = 0; e < NEXP; e++) d_cursor[e] = d_offsets[e];
}

__global__ void assign_kernel() {
    int t = blockIdx.x * blockDim.x + threadIdx.x;
    if (t >= T_TOK) return;
    int p0 = atomicAdd(&d_cursor[d_ea[t]], 1);
    d_row_token[p0] = t;
    d_token_pos[2 * t] = p0;
    int p1 = atomicAdd(&d_cursor[d_eb[t]], 1);
    d_row_token[p1] = t;
    d_token_pos[2 * t + 1] = p1;
}

// ---------------- f32x2 GEMM, conflict-free duplicated-A feed (R11 core) ----------
// MODE 0: d_h = gather(x) @ w1e   (K=HID, N=FF2)
// MODE 1: d_y = d_g      @ w2e    (K=FF,  N=HID)
// CTA 128m x 128n, BK=16, 128 threads, micro-tile 8m x 16n (8 f32x2 col-pairs).
template <int MODE>
__global__ void __launch_bounds__(128, 2)
gemm2x_kernel(const float* __restrict__ Xin, const float* __restrict__ Wbase) {
    constexpr int Kd = (MODE == 0) ? HID : FF;
    constexpr int Nd = (MODE == 0) ? FF2 : HID;

    int e = blockIdx.z;
    int seg0 = d_offsets[e], seg1 = d_offsets[e + 1];
    int row0 = seg0 + blockIdx.x * 128;
    if (row0 >= seg1) return;
    int col0 = blockIdx.y * 128;

    __shared__ float2 As2[BK][136];
    __shared__ float  Bs[BK][128];

    int tid = threadIdx.x;
    int tx = tid & 7, ty = tid >> 3;

    const float* W = Wbase + (size_t)e * Kd * Nd + col0;

    int grow = row0 + tid;
    bool a_valid = grow < seg1;
    int asrc = a_valid ? grow : (seg1 - 1);
    const float* Arow;
    if (MODE == 0) {
        int t = d_row_token[asrc];
        Arow = Xin + ((size_t)(t % S_LEN) * B_SZ + (t / S_LEN)) * HID;
    } else {
        Arow = d_g + (size_t)asrc * Kd;
    }
    int pa = tid + (tid >> 4);
    int abase = ty * 8 + (ty >> 1);

    unsigned long long acc2[8][8];
#pragma unroll
    for (int i = 0; i < 8; i++)
#pragma unroll
        for (int j = 0; j < 8; j++) acc2[i][j] = 0ull;

    for (int k0 = 0; k0 < Kd; k0 += BK) {
        __syncthreads();
#pragma unroll
        for (int c = 0; c < 4; c++) {
            float4 v = a_valid ? *(const float4*)(Arow + k0 + c * 4)
                               : make_float4(0.f, 0.f, 0.f, 0.f);
            As2[c * 4 + 0][pa] = make_float2(v.x, v.x);
            As2[c * 4 + 1][pa] = make_float2(v.y, v.y);
            As2[c * 4 + 2][pa] = make_float2(v.z, v.z);
            As2[c * 4 + 3][pa] = make_float2(v.w, v.w);
        }
#pragma unroll
        for (int q = 0; q < 4; q++) {
            int idx = q * 128 + tid;
            int br = idx >> 5, bc = (idx & 31) * 4;
            *(float4*)&Bs[br][bc] = *(const float4*)(W + (size_t)(k0 + br) * Nd + bc);
        }
        __syncthreads();

#pragma unroll
        for (int k = 0; k < BK; k++) {
            unsigned long long bv[8], av[8];
#pragma unroll
            for (int j = 0; j < 8; j++)
                bv[j] = *(const unsigned long long*)&Bs[k][j * 16 + tx * 2];
#pragma unroll
            for (int i = 0; i < 8; i++)
                av[i] = *(const unsigned long long*)&As2[k][abase + i];
#pragma unroll
            for (int i = 0; i < 8; i++)
#pragma unroll
                for (int j = 0; j < 8; j++)
                    asm("fma.rn.f32x2 %0, %1, %2, %0;"
                        : "+l"(acc2[i][j]) : "l"(av[i]), "l"(bv[j]));
        }
    }

    float* C = (MODE == 0) ? d_h : d_y;
#pragma unroll
    for (int i = 0; i < 8; i++) {
        int gr = row0 + ty * 8 + i;
        if (gr < seg1) {
            float* crow = C + (size_t)gr * Nd + col0;
#pragma unroll
            for (int j = 0; j < 8; j++)
                *(unsigned long long*)(crow + j * 16 + tx * 2) = acc2[i][j];
        }
    }
}

// ---------------- swiglu ----------------
__global__ void swiglu_kernel() {
    int r = blockIdx.x;
    const float* hr = d_h + (size_t)r * FF2;
    float2* gf = (float2*)(d_g + (size_t)r * FF);
    for (int j = threadIdx.x; j < FF / 2; j += 256) {
        float2 a = ((const float2*)hr)[j];
        float2 b = ((const float2*)(hr + FF))[j];
        float y0 = (a.x / (1.f + expf(-a.x))) * b.x;
        float y1 = (a.y / (1.f + expf(-a.y))) * b.y;
        gf[j] = make_float2(y0, y1);
    }
}

// ---------------- combine ----------------
__global__ void combine_kernel(float* __restrict__ out) {
    int v = blockIdx.x * blockDim.x + threadIdx.x;
    const int total = T_TOK * (HID / 4);
    if (v >= total) return;
    int t = v / (HID / 4);
    int h4 = v % (HID / 4);
    int p0 = d_token_pos[2 * t], p1 = d_token_pos[2 * t + 1];
    float wa = d_wa[t], wb = d_wb[t];
    const float4 y0 = *(const float4*)&d_y[(size_t)p0 * HID + h4 * 4];
    const float4 y1 = *(const float4*)&d_y[(size_t)p1 * HID + h4 * 4];
    float4 o;
    o.x = wa * y0.x + wb * y1.x;
    o.y = wa * y0.y + wb * y1.y;
    o.z = wa * y0.z + wb * y1.z;
    o.w = wa * y0.w + wb * y1.w;
    int s = t % S_LEN, b = t / S_LEN;
    *(float4*)&out[((size_t)s * B_SZ + b) * HID + h4 * 4] = o;
}

// ---------------- launch ----------------
extern "C" void kernel_launch(void* const* d_in, const int* in_sizes, int n_in,
                              void* d_out, int out_size) {
    const float* x  = (const float*)d_in[0];
    const float* wg = (const float*)d_in[1];
    const float* w1 = (const float*)d_in[2];
    const float* w2 = (const float*)d_in[3];
    float* out = (float*)d_out;

    zero_counts_kernel<<<1, 32>>>();
    gate_kernel<<<T_TOK / 4, 256>>>(x, wg);
    scan_kernel<<<1, 1>>>();
    assign_kernel<<<T_TOK / 256, 256>>>();

    gemm2x_kernel<0><<<dim3(128, FF2 / 128, NEXP), 128>>>(x, w1);
    swiglu_kernel<<<NROWS, 256>>>();
    gemm2x_kernel<1><<<dim3(128, HID / 128, NEXP), 128>>>(nullptr, w2);
    combine_kernel<<<(T_TOK * (HID / 4)) / 256, 256>>>(out);
}

// round 15
// speedup vs baseline: 2.9980x; 1.6984x over previous
#include <cuda_runtime.h>
#include <cstdint>

// Problem constants
#define S_LEN 2048
#define B_SZ 4
#define HID 2048
#define T_TOK 8192
#define FF 1408
#define FF2 2816
#define NEXP 8
#define NROWS 16384
#define BK 16

// ---------------- scratch (device globals) ----------------
__device__ int   d_counts[NEXP];
__device__ int   d_offsets[NEXP + 1];
__device__ int   d_cursor[NEXP];
__device__ int   d_ea[T_TOK];
__device__ int   d_eb[T_TOK];
__device__ float d_wa[T_TOK];
__device__ float d_wb[T_TOK];
__device__ int   d_row_token[NROWS];
__device__ int   d_token_pos[T_TOK * 2];
__device__ float d_h[(size_t)NROWS * FF2];
__device__ float d_g[(size_t)NROWS * FF];
__device__ float d_y[(size_t)NROWS * HID];

// ---------------- routing (R11-proven, 1 token per block) ----------------
__global__ void zero_counts_kernel() {
    if (threadIdx.x < NEXP) d_counts[threadIdx.x] = 0;
}

__global__ void gate_kernel(const float* __restrict__ x, const float* __restrict__ wg) {
    int t = blockIdx.x;
    const float* xr = x + ((size_t)(t % S_LEN) * B_SZ + (t / S_LEN)) * HID;
    float acc[NEXP];
#pragma unroll
    for (int e = 0; e < NEXP; e++) acc[e] = 0.f;
    for (int h = threadIdx.x; h < HID; h += 256) {
        float xv = xr[h];
#pragma unroll
        for (int e = 0; e < NEXP; e++) acc[e] += xv * wg[e * HID + h];
    }
#pragma unroll
    for (int e = 0; e < NEXP; e++)
        for (int off = 16; off; off >>= 1)
            acc[e] += __shfl_down_sync(0xffffffffu, acc[e], off);
    __shared__ float red[8][NEXP];
    int warp = threadIdx.x >> 5, lane = threadIdx.x & 31;
    if (lane == 0)
#pragma unroll
        for (int e = 0; e < NEXP; e++) red[warp][e] = acc[e];
    __syncthreads();
    if (threadIdx.x == 0) {
        float logits[NEXP];
#pragma unroll
        for (int e = 0; e < NEXP; e++) {
            float s = 0.f;
            for (int w = 0; w < 8; w++) s += red[w][e];
            logits[e] = s;
        }
        float m = logits[0];
#pragma unroll
        for (int e = 1; e < NEXP; e++) m = fmaxf(m, logits[e]);
        float sc[NEXP], Z = 0.f;
#pragma unroll
        for (int e = 0; e < NEXP; e++) { sc[e] = expf(logits[e] - m); Z += sc[e]; }
        float invZ = 1.f / Z;
#pragma unroll
        for (int e = 0; e < NEXP; e++) sc[e] *= invZ;
        int e0 = 0;
#pragma unroll
        for (int e = 1; e < NEXP; e++) if (sc[e] > sc[e0]) e0 = e;
        int e1 = (e0 == 0) ? 1 : 0;
#pragma unroll
        for (int e = 0; e < NEXP; e++) if (e != e0 && sc[e] > sc[e1]) e1 = e;
        float s0 = sc[e0], s1 = sc[e1];
        float inv = 1.f / (s0 + s1 + 1e-20f);
        d_ea[t] = e0; d_eb[t] = e1;
        d_wa[t] = s0 * inv; d_wb[t] = s1 * inv;
        atomicAdd(&d_counts[e0], 1);
        atomicAdd(&d_counts[e1], 1);
    }
}

__global__ void scan_kernel() {
    int o = 0;
    d_offsets[0] = 0;
#pragma unroll
    for (int e = 0; e < NEXP; e++) { o += d_counts[e]; d_offsets[e + 1] = o; }
#pragma unroll
    for (int e = 0; e < NEXP; e++) d_cursor[e] = d_offsets[e];
}

__global__ void assign_kernel() {
    int t = blockIdx.x * blockDim.x + threadIdx.x;
    if (t >= T_TOK) return;
    int p0 = atomicAdd(&d_cursor[d_ea[t]], 1);
    d_row_token[p0] = t;
    d_token_pos[2 * t] = p0;
    int p1 = atomicAdd(&d_cursor[d_eb[t]], 1);
    d_row_token[p1] = t;
    d_token_pos[2 * t + 1] = p1;
}

// ---------------- f32x2 GEMM, LDS.128-packed fragment feed ----------------
// MODE 0: d_h = gather(x) @ w1e   (K=HID, N=FF2)
// MODE 1: d_y = d_g      @ w2e    (K=FF,  N=HID)
// CTA 128m x 128n, BK=16, 128 threads, micro-tile 8m x 16n.
// A: duplicated {a,a} pairs, pad 2 pairs/16 rows -> thread's 8 pairs contiguous,
//    16B-aligned, per-warp conflict-free.
// B: permuted pair-packed Bp[k][tx*10 + j] = (W[k][j*16+tx*2], W[k][j*16+tx*2+1])
//    -> thread's 8 pairs contiguous; x10 skew de-conflicts banks.
template <int MODE>
__global__ void __launch_bounds__(128, 2)
gemm2x_kernel(const float* __restrict__ Xin, const float* __restrict__ Wbase) {
    constexpr int Kd = (MODE == 0) ? HID : FF;
    constexpr int Nd = (MODE == 0) ? FF2 : HID;

    int e = blockIdx.z;
    int seg0 = d_offsets[e], seg1 = d_offsets[e + 1];
    int row0 = seg0 + blockIdx.x * 128;
    if (row0 >= seg1) return;
    int col0 = blockIdx.y * 128;

    __shared__ __align__(16) float2 As2[BK][144];   // 18432 B
    __shared__ __align__(16) float2 Bp[BK][80];     // 10240 B

    int tid = threadIdx.x;
    int tx = tid & 7, ty = tid >> 3;

    const float* W = Wbase + (size_t)e * Kd * Nd + col0;

    int grow = row0 + tid;
    bool a_valid = grow < seg1;
    int asrc = a_valid ? grow : (seg1 - 1);
    const float* Arow;
    if (MODE == 0) {
        int t = d_row_token[asrc];
        Arow = Xin + ((size_t)(t % S_LEN) * B_SZ + (t / S_LEN)) * HID;
    } else {
        Arow = d_g + (size_t)asrc * Kd;
    }
    int pa = tid + 2 * (tid >> 4);           // physical dup-A pair index for row tid
    int abase = ty * 8 + 2 * (ty >> 1);      // fragment base (16B-aligned: even)
    int bbase = tx * 10;                     // fragment base in Bp (even)

    unsigned long long acc2[8][8];
#pragma unroll
    for (int i = 0; i < 8; i++)
#pragma unroll
        for (int j = 0; j < 8; j++) acc2[i][j] = 0ull;

    for (int k0 = 0; k0 < Kd; k0 += BK) {
        __syncthreads();
        // A: 16 floats of this thread's row -> duplicated pairs
#pragma unroll
        for (int c = 0; c < 4; c++) {
            float4 v = a_valid ? *(const float4*)(Arow + k0 + c * 4)
                               : make_float4(0.f, 0.f, 0.f, 0.f);
            As2[c * 4 + 0][pa] = make_float2(v.x, v.x);
            As2[c * 4 + 1][pa] = make_float2(v.y, v.y);
            As2[c * 4 + 2][pa] = make_float2(v.z, v.z);
            As2[c * 4 + 3][pa] = make_float2(v.w, v.w);
        }
        // B: coalesced float4 loads, scattered pair-packed stores
#pragma unroll
        for (int q = 0; q < 4; q++) {
            int idx = q * 128 + tid;
            int br = idx >> 5, bc = (idx & 31) * 4;
            float4 v = *(const float4*)(W + (size_t)(k0 + br) * Nd + bc);
            int p0 = (idx & 31) * 2;             // pair index = col/2
            int p1 = p0 + 1;
            Bp[br][(p0 & 7) * 10 + (p0 >> 3)] = make_float2(v.x, v.y);
            Bp[br][(p1 & 7) * 10 + (p1 >> 3)] = make_float2(v.z, v.w);
        }
        __syncthreads();

#pragma unroll
        for (int k = 0; k < BK; k++) {
            unsigned long long av[8], bv[8];
#pragma unroll
            for (int m = 0; m < 4; m++) {
                ulonglong2 ta = *(const ulonglong2*)&As2[k][abase + 2 * m];
                av[2 * m] = ta.x; av[2 * m + 1] = ta.y;
                ulonglong2 tb = *(const ulonglong2*)&Bp[k][bbase + 2 * m];
                bv[2 * m] = tb.x; bv[2 * m + 1] = tb.y;
            }
#pragma unroll
            for (int i = 0; i < 8; i++)
#pragma unroll
                for (int j = 0; j < 8; j++)
                    asm("fma.rn.f32x2 %0, %1, %2, %0;"
                        : "+l"(acc2[i][j]) : "l"(av[i]), "l"(bv[j]));
        }
    }

    float* C = (MODE == 0) ? d_h : d_y;
#pragma unroll
    for (int i = 0; i < 8; i++) {
        int gr = row0 + ty * 8 + i;
        if (gr < seg1) {
            float* crow = C + (size_t)gr * Nd + col0;
#pragma unroll
            for (int j = 0; j < 8; j++)
                *(unsigned long long*)(crow + j * 16 + tx * 2) = acc2[i][j];
        }
    }
}

// ---------------- swiglu ----------------
__global__ void swiglu_kernel() {
    int r = blockIdx.x;
    const float* hr = d_h + (size_t)r * FF2;
    float2* gf = (float2*)(d_g + (size_t)r * FF);
    for (int j = threadIdx.x; j < FF / 2; j += 256) {
        float2 a = ((const float2*)hr)[j];
        float2 b = ((const float2*)(hr + FF))[j];
        float y0 = (a.x / (1.f + expf(-a.x))) * b.x;
        float y1 = (a.y / (1.f + expf(-a.y))) * b.y;
        gf[j] = make_float2(y0, y1);
    }
}

// ---------------- combine ----------------
__global__ void combine_kernel(float* __restrict__ out) {
    int v = blockIdx.x * blockDim.x + threadIdx.x;
    const int total = T_TOK * (HID / 4);
    if (v >= total) return;
    int t = v / (HID / 4);
    int h4 = v % (HID / 4);
    int p0 = d_token_pos[2 * t], p1 = d_token_pos[2 * t + 1];
    float wa = d_wa[t], wb = d_wb[t];
    const float4 y0 = *(const float4*)&d_y[(size_t)p0 * HID + h4 * 4];
    const float4 y1 = *(const float4*)&d_y[(size_t)p1 * HID + h4 * 4];
    float4 o;
    o.x = wa * y0.x + wb * y1.x;
    o.y = wa * y0.y + wb * y1.y;
    o.z = wa * y0.z + wb * y1.z;
    o.w = wa * y0.w + wb * y1.w;
    int s = t % S_LEN, b = t / S_LEN;
    *(float4*)&out[((size_t)s * B_SZ + b) * HID + h4 * 4] = o;
}

// ---------------- launch ----------------
extern "C" void kernel_launch(void* const* d_in, const int* in_sizes, int n_in,
                              void* d_out, int out_size) {
    const float* x  = (const float*)d_in[0];
    const float* wg = (const float*)d_in[1];
    const float* w1 = (const float*)d_in[2];
    const float* w2 = (const float*)d_in[3];
    float* out = (float*)d_out;

    zero_counts_kernel<<<1, 32>>>();
    gate_kernel<<<T_TOK, 256>>>(x, wg);
    scan_kernel<<<1, 1>>>();
    assign_kernel<<<T_TOK / 256, 256>>>();

    gemm2x_kernel<0><<<dim3(128, FF2 / 128, NEXP), 128>>>(x, w1);
    swiglu_kernel<<<NROWS, 256>>>();
    gemm2x_kernel<1><<<dim3(128, HID / 128, NEXP), 128>>>(nullptr, w2);
    combine_kernel<<<(T_TOK * (HID / 4)) / 256, 256>>>(out);
}

// round 16
// speedup vs baseline: 3.0786x; 1.0269x over previous
#include <cuda_runtime.h>
#include <cstdint>

// Problem constants
#define S_LEN 2048
#define B_SZ 4
#define HID 2048
#define T_TOK 8192
#define FF 1408
#define FF2 2816
#define NEXP 8
#define NROWS 16384
#define BK 16

// ---------------- scratch (device globals) ----------------
__device__ int   d_counts[NEXP];
__device__ int   d_offsets[NEXP + 1];
__device__ int   d_cursor[NEXP];
__device__ int   d_ea[T_TOK];
__device__ int   d_eb[T_TOK];
__device__ float d_wa[T_TOK];
__device__ float d_wb[T_TOK];
__device__ int   d_row_token[NROWS];
__device__ int   d_token_pos[T_TOK * 2];
__device__ float d_h[(size_t)NROWS * FF2];
__device__ float d_g[(size_t)NROWS * FF];
__device__ float d_y[(size_t)NROWS * HID];

// ---------------- routing (proven) ----------------
__global__ void zero_counts_kernel() {
    if (threadIdx.x < NEXP) d_counts[threadIdx.x] = 0;
}

__global__ void gate_kernel(const float* __restrict__ x, const float* __restrict__ wg) {
    int t = blockIdx.x;
    const float* xr = x + ((size_t)(t % S_LEN) * B_SZ + (t / S_LEN)) * HID;
    float acc[NEXP];
#pragma unroll
    for (int e = 0; e < NEXP; e++) acc[e] = 0.f;
    for (int h = threadIdx.x; h < HID; h += 256) {
        float xv = xr[h];
#pragma unroll
        for (int e = 0; e < NEXP; e++) acc[e] += xv * wg[e * HID + h];
    }
#pragma unroll
    for (int e = 0; e < NEXP; e++)
        for (int off = 16; off; off >>= 1)
            acc[e] += __shfl_down_sync(0xffffffffu, acc[e], off);
    __shared__ float red[8][NEXP];
    int warp = threadIdx.x >> 5, lane = threadIdx.x & 31;
    if (lane == 0)
#pragma unroll
        for (int e = 0; e < NEXP; e++) red[warp][e] = acc[e];
    __syncthreads();
    if (threadIdx.x == 0) {
        float logits[NEXP];
#pragma unroll
        for (int e = 0; e < NEXP; e++) {
            float s = 0.f;
            for (int w = 0; w < 8; w++) s += red[w][e];
            logits[e] = s;
        }
        float m = logits[0];
#pragma unroll
        for (int e = 1; e < NEXP; e++) m = fmaxf(m, logits[e]);
        float sc[NEXP], Z = 0.f;
#pragma unroll
        for (int e = 0; e < NEXP; e++) { sc[e] = expf(logits[e] - m); Z += sc[e]; }
        float invZ = 1.f / Z;
#pragma unroll
        for (int e = 0; e < NEXP; e++) sc[e] *= invZ;
        int e0 = 0;
#pragma unroll
        for (int e = 1; e < NEXP; e++) if (sc[e] > sc[e0]) e0 = e;
        int e1 = (e0 == 0) ? 1 : 0;
#pragma unroll
        for (int e = 0; e < NEXP; e++) if (e != e0 && sc[e] > sc[e1]) e1 = e;
        float s0 = sc[e0], s1 = sc[e1];
        float inv = 1.f / (s0 + s1 + 1e-20f);
        d_ea[t] = e0; d_eb[t] = e1;
        d_wa[t] = s0 * inv; d_wb[t] = s1 * inv;
        atomicAdd(&d_counts[e0], 1);
        atomicAdd(&d_counts[e1], 1);
    }
}

__global__ void scan_kernel() {
    int o = 0;
    d_offsets[0] = 0;
#pragma unroll
    for (int e = 0; e < NEXP; e++) { o += d_counts[e]; d_offsets[e + 1] = o; }
#pragma unroll
    for (int e = 0; e < NEXP; e++) d_cursor[e] = d_offsets[e];
}

__global__ void assign_kernel() {
    int t = blockIdx.x * blockDim.x + threadIdx.x;
    if (t >= T_TOK) return;
    int p0 = atomicAdd(&d_cursor[d_ea[t]], 1);
    d_row_token[p0] = t;
    d_token_pos[2 * t] = p0;
    int p1 = atomicAdd(&d_cursor[d_eb[t]], 1);
    d_row_token[p1] = t;
    d_token_pos[2 * t + 1] = p1;
}

// ---------------- f32x2 GEMM, LDS.128 fragments + register prefetch ----------------
// MODE 0: d_h = gather(x) @ w1e   (K=HID, N=FF2)
// MODE 1: d_y = d_g      @ w2e    (K=FF,  N=HID)
// CTA 128m x 128n, BK=16, 128 threads, micro-tile 8m x 16n. R15 fragment scheme.
template <int MODE>
__global__ void __launch_bounds__(128, 2)
gemm2x_kernel(const float* __restrict__ Xin, const float* __restrict__ Wbase) {
    constexpr int Kd = (MODE == 0) ? HID : FF;
    constexpr int Nd = (MODE == 0) ? FF2 : HID;
    constexpr int NC = Kd / BK;

    int e = blockIdx.z;
    int seg0 = d_offsets[e], seg1 = d_offsets[e + 1];
    int row0 = seg0 + blockIdx.x * 128;
    if (row0 >= seg1) return;
    int col0 = blockIdx.y * 128;

    __shared__ __align__(16) float2 As2[BK][144];
    __shared__ __align__(16) float2 Bp[BK][80];

    int tid = threadIdx.x;
    int tx = tid & 7, ty = tid >> 3;

    const float* W = Wbase + (size_t)e * Kd * Nd + col0;

    int grow = row0 + tid;
    bool a_valid = grow < seg1;
    int asrc = a_valid ? grow : (seg1 - 1);
    const float* Arow;
    if (MODE == 0) {
        int t = d_row_token[asrc];
        Arow = Xin + ((size_t)(t % S_LEN) * B_SZ + (t / S_LEN)) * HID;
    } else {
        Arow = d_g + (size_t)asrc * Kd;
    }
    int pa = tid + 2 * (tid >> 4);
    int abase = ty * 8 + 2 * (ty >> 1);
    int bbase = tx * 10;

    // per-thread B load slots (fixed across chunks)
    int bidx[4], brow[4], bcol[4];
#pragma unroll
    for (int q = 0; q < 4; q++) {
        bidx[q] = q * 128 + tid;
        brow[q] = bidx[q] >> 5;
        bcol[q] = (bidx[q] & 31) * 4;
    }

    unsigned long long acc2[8][8];
#pragma unroll
    for (int i = 0; i < 8; i++)
#pragma unroll
        for (int j = 0; j < 8; j++) acc2[i][j] = 0ull;

    // prefetch chunk 0 into registers
    float4 rA[4], rB[4];
#pragma unroll
    for (int c = 0; c < 4; c++)
        rA[c] = a_valid ? *(const float4*)(Arow + c * 4)
                        : make_float4(0.f, 0.f, 0.f, 0.f);
#pragma unroll
    for (int q = 0; q < 4; q++)
        rB[q] = *(const float4*)(W + (size_t)brow[q] * Nd + bcol[q]);

    for (int i = 0; i < NC; i++) {
        __syncthreads();   // previous chunk's compute done
        // store prefetched registers into smem
#pragma unroll
        for (int c = 0; c < 4; c++) {
            As2[c * 4 + 0][pa] = make_float2(rA[c].x, rA[c].x);
            As2[c * 4 + 1][pa] = make_float2(rA[c].y, rA[c].y);
            As2[c * 4 + 2][pa] = make_float2(rA[c].z, rA[c].z);
            As2[c * 4 + 3][pa] = make_float2(rA[c].w, rA[c].w);
        }
#pragma unroll
        for (int q = 0; q < 4; q++) {
            int p0 = (bidx[q] & 31) * 2;
            int p1 = p0 + 1;
            Bp[brow[q]][(p0 & 7) * 10 + (p0 >> 3)] = make_float2(rB[q].x, rB[q].y);
            Bp[brow[q]][(p1 & 7) * 10 + (p1 >> 3)] = make_float2(rB[q].z, rB[q].w);
        }
        __syncthreads();

        // issue next chunk's global loads (latency hidden by compute below)
        if (i + 1 < NC) {
            int k0n = (i + 1) * BK;
#pragma unroll
            for (int c = 0; c < 4; c++)
                rA[c] = a_valid ? *(const float4*)(Arow + k0n + c * 4)
                                : make_float4(0.f, 0.f, 0.f, 0.f);
#pragma unroll
            for (int q = 0; q < 4; q++)
                rB[q] = *(const float4*)(W + (size_t)(k0n + brow[q]) * Nd + bcol[q]);
        }

#pragma unroll
        for (int k = 0; k < BK; k++) {
            unsigned long long av[8], bv[8];
#pragma unroll
            for (int m = 0; m < 4; m++) {
                ulonglong2 ta = *(const ulonglong2*)&As2[k][abase + 2 * m];
                av[2 * m] = ta.x; av[2 * m + 1] = ta.y;
                ulonglong2 tb = *(const ulonglong2*)&Bp[k][bbase + 2 * m];
                bv[2 * m] = tb.x; bv[2 * m + 1] = tb.y;
            }
#pragma unroll
            for (int ii = 0; ii < 8; ii++)
#pragma unroll
                for (int j = 0; j < 8; j++)
                    asm("fma.rn.f32x2 %0, %1, %2, %0;"
                        : "+l"(acc2[ii][j]) : "l"(av[ii]), "l"(bv[j]));
        }
    }

    float* C = (MODE == 0) ? d_h : d_y;
#pragma unroll
    for (int i = 0; i < 8; i++) {
        int gr = row0 + ty * 8 + i;
        if (gr < seg1) {
            float* crow = C + (size_t)gr * Nd + col0;
#pragma unroll
            for (int j = 0; j < 8; j++)
                *(unsigned long long*)(crow + j * 16 + tx * 2) = acc2[i][j];
        }
    }
}

// ---------------- swiglu ----------------
__global__ void swiglu_kernel() {
    int r = blockIdx.x;
    const float* hr = d_h + (size_t)r * FF2;
    float2* gf = (float2*)(d_g + (size_t)r * FF);
    for (int j = threadIdx.x; j < FF / 2; j += 256) {
        float2 a = ((const float2*)hr)[j];
        float2 b = ((const float2*)(hr + FF))[j];
        float y0 = (a.x / (1.f + expf(-a.x))) * b.x;
        float y1 = (a.y / (1.f + expf(-a.y))) * b.y;
        gf[j] = make_float2(y0, y1);
    }
}

// ---------------- combine ----------------
__global__ void combine_kernel(float* __restrict__ out) {
    int v = blockIdx.x * blockDim.x + threadIdx.x;
    const int total = T_TOK * (HID / 4);
    if (v >= total) return;
    int t = v / (HID / 4);
    int h4 = v % (HID / 4);
    int p0 = d_token_pos[2 * t], p1 = d_token_pos[2 * t + 1];
    float wa = d_wa[t], wb = d_wb[t];
    const float4 y0 = *(const float4*)&d_y[(size_t)p0 * HID + h4 * 4];
    const float4 y1 = *(const float4*)&d_y[(size_t)p1 * HID + h4 * 4];
    float4 o;
    o.x = wa * y0.x + wb * y1.x;
    o.y = wa * y0.y + wb * y1.y;
    o.z = wa * y0.z + wb * y1.z;
    o.w = wa * y0.w + wb * y1.w;
    int s = t % S_LEN, b = t / S_LEN;
    *(float4*)&out[((size_t)s * B_SZ + b) * HID + h4 * 4] = o;
}

// ---------------- launch ----------------
extern "C" void kernel_launch(void* const* d_in, const int* in_sizes, int n_in,
                              void* d_out, int out_size) {
    const float* x  = (const float*)d_in[0];
    const float* wg = (const float*)d_in[1];
    const float* w1 = (const float*)d_in[2];
    const float* w2 = (const float*)d_in[3];
    float* out = (float*)d_out;

    zero_counts_kernel<<<1, 32>>>();
    gate_kernel<<<T_TOK, 256>>>(x, wg);
    scan_kernel<<<1, 1>>>();
    assign_kernel<<<T_TOK / 256, 256>>>();

    gemm2x_kernel<0><<<dim3(128, FF2 / 128, NEXP), 128>>>(x, w1);
    swiglu_kernel<<<NROWS, 256>>>();
    gemm2x_kernel<1><<<dim3(128, HID / 128, NEXP), 128>>>(nullptr, w2);
    combine_kernel<<<(T_TOK * (HID / 4)) / 256, 256>>>(out);
}